// round 15
// baseline (speedup 1.0000x reference)
#include <cuda_runtime.h>
#include <cuda_fp16.h>
#include <math.h>
#include <stdint.h>

// ---------------------------------------------------------------------------
// Problem constants
// ---------------------------------------------------------------------------
#define NT   2048
#define DM   2048
#define NE   64
#define TOPK 4
#define FF   512
#define NS   2
#define SFF  2048
#define CAP  256
#define NP   (NT * TOPK)

// ---------------------------------------------------------------------------
// Device scratch
// ---------------------------------------------------------------------------
__device__ float  g_logits[NT * NE];
__device__ int    g_tok_table[NE * CAP];
__device__ float  g_w_slot[NE * CAP];
__device__ int    g_counts[NE];
__device__ __half g_xh[NT * DM];
__device__ __half g_h [NE * CAP * FF];
__device__ __half g_hs[NS * NT * SFF];

// ---------------------------------------------------------------------------
// Helpers
// ---------------------------------------------------------------------------
__device__ __forceinline__ uint32_t smem_u32(const void* p) {
    uint32_t a;
    asm("{ .reg .u64 t; cvta.to.shared.u64 t, %1; cvt.u32.u64 %0, t; }" : "=r"(a) : "l"(p));
    return a;
}
__device__ __forceinline__ void ldsm4(uint32_t r[4], uint32_t a) {
    asm volatile("ldmatrix.sync.aligned.m8n8.x4.shared.b16 {%0,%1,%2,%3}, [%4];"
        : "=r"(r[0]), "=r"(r[1]), "=r"(r[2]), "=r"(r[3]) : "r"(a));
}
__device__ __forceinline__ void mma_f16(float c[4], const uint32_t a[4], const uint32_t b[2]) {
    asm volatile("mma.sync.aligned.m16n8k16.row.col.f32.f16.f16.f32 "
        "{%0,%1,%2,%3}, {%4,%5,%6,%7}, {%8,%9}, {%0,%1,%2,%3};"
        : "+f"(c[0]), "+f"(c[1]), "+f"(c[2]), "+f"(c[3])
        : "r"(a[0]), "r"(a[1]), "r"(a[2]), "r"(a[3]), "r"(b[0]), "r"(b[1]));
}
__device__ __forceinline__ uint32_t h2u(__half2 h) { return *(uint32_t*)&h; }

#define SST_B 144

__device__ __forceinline__ void cvt_storeBh(float4 v, char* hi, int r, int c4) {
    __half2 h0 = __floats2half2_rn(v.x, v.y);
    __half2 h1 = __floats2half2_rn(v.z, v.w);
    *(uint2*)(hi + (uint32_t)(r * SST_B + c4 * 2)) = make_uint2(h2u(h0), h2u(h1));
}
__device__ __forceinline__ float silu_f(float g) { return g / (1.f + expf(-g)); }

// Stage layouts: 64M tiles; each stage = TWO 64-K subtiles; 2-stage ring.
#define GA 9216                            // A: 64 rows * 144B
#define GB 9216                            // B matrix: 64 rows * 144B
#define DB 18432                           // DN B: 128 rows * 144B
#define GU_SUB (GA + 2 * GB)               // 27648 : A | Bg | Bu
#define DN_SUB (GA + DB)                   // 27648 : A | B
#define GU_STG (2 * GU_SUB)                // 55296
#define DN_STG (2 * DN_SUB)                // 55296
#define S_STAGES 2
#define GU_SMEM (S_STAGES * GU_STG)        // 110592  -> 2 CTAs/SM
#define DN_SMEM (S_STAGES * DN_STG)        // 110592

// Named barriers (256-thread CTA): FULL(s)=1+s, EMPTY(s)=3+s
#define BAR_SYNC(id)   asm volatile("bar.sync %0, 256;"   :: "r"(id) : "memory")
#define BAR_ARRIVE(id) asm volatile("bar.arrive %0, 256;" :: "r"(id) : "memory")

// ===========================================================================
// 0) x -> fp16, zero counts/tables/out
// ===========================================================================
__global__ __launch_bounds__(256)
void k_cvt_x(const float* __restrict__ x, float* __restrict__ out)
{
    int gtid = blockIdx.x * 256 + threadIdx.x;
    if (blockIdx.x == 0 && threadIdx.x < NE) g_counts[threadIdx.x] = 0;
    if (gtid < NE * CAP) {
        g_tok_table[gtid] = 0;
        g_w_slot[gtid]    = 0.f;
    }
    int i = gtid * 4;
    float4 v = *(const float4*)(x + i);
    __half2 h0 = __floats2half2_rn(v.x, v.y);
    __half2 h1 = __floats2half2_rn(v.z, v.w);
    *(uint2*)(g_xh + i) = make_uint2(h2u(h0), h2u(h1));
    *(float4*)(out + i) = make_float4(0.f, 0.f, 0.f, 0.f);
}

// ===========================================================================
// 1) Router logits (SIMT fp32)
// ===========================================================================
#define RBM 64
#define RBK 16
__global__ __launch_bounds__(256)
void k_router_logits(const float* __restrict__ x, const float* __restrict__ rw)
{
    __shared__ __align__(16) float As[RBK][RBM];
    __shared__ __align__(16) float Bs[RBK][RBM];
    const int tid = threadIdx.x;
    const int t0  = blockIdx.x * RBM;
    const int lr  = tid >> 2, lk = (tid & 3) * 4;
    const int ty4 = (tid >> 4) * 4, tx4 = (tid & 15) * 4;
    float acc[4][4];
#pragma unroll
    for (int i = 0; i < 4; i++)
#pragma unroll
        for (int j = 0; j < 4; j++) acc[i][j] = 0.f;
    for (int kt = 0; kt < DM; kt += RBK) {
        float4 a = *(const float4*)(x + (size_t)(t0 + lr) * DM + kt + lk);
        As[lk+0][lr] = a.x; As[lk+1][lr] = a.y; As[lk+2][lr] = a.z; As[lk+3][lr] = a.w;
        float4 b = *(const float4*)(rw + (size_t)lr * DM + kt + lk);
        Bs[lk+0][lr] = b.x; Bs[lk+1][lr] = b.y; Bs[lk+2][lr] = b.z; Bs[lk+3][lr] = b.w;
        __syncthreads();
#pragma unroll
        for (int k = 0; k < RBK; k++) {
            float4 av = *(const float4*)&As[k][ty4];
            float4 bv = *(const float4*)&Bs[k][tx4];
            float a4[4] = {av.x, av.y, av.z, av.w};
            float b4[4] = {bv.x, bv.y, bv.z, bv.w};
#pragma unroll
            for (int i = 0; i < 4; i++)
#pragma unroll
                for (int j = 0; j < 4; j++) acc[i][j] += a4[i] * b4[j];
        }
        __syncthreads();
    }
#pragma unroll
    for (int i = 0; i < 4; i++)
#pragma unroll
        for (int j = 0; j < 4; j++)
            g_logits[(size_t)(t0 + ty4 + i) * NE + tx4 + j] = acc[i][j];
}

// ===========================================================================
// 2) Top-k + dispatch fused (1 warp / token)
// ===========================================================================
__global__ void k_topk_dispatch(const float* __restrict__ bias)
{
    const int n = blockIdx.x, lane = threadIdx.x;
    float l0 = g_logits[n * NE + lane];
    float l1 = g_logits[n * NE + 32 + lane];
    float s0 = l0 + bias[lane];
    float s1 = l1 + bias[32 + lane];
    int ch_idx[TOPK]; float ch_l[TOPK];
#pragma unroll
    for (int r = 0; r < TOPK; r++) {
        float v = s0; int idx = lane;
        if (s1 > v) { v = s1; idx = lane + 32; }
#pragma unroll
        for (int off = 16; off > 0; off >>= 1) {
            float ov = __shfl_xor_sync(0xffffffffu, v, off);
            int   oi = __shfl_xor_sync(0xffffffffu, idx, off);
            if (ov > v || (ov == v && oi < idx)) { v = ov; idx = oi; }
        }
        int owner = (idx < 32) ? idx : (idx - 32);
        float rawA = __shfl_sync(0xffffffffu, l0, owner);
        float rawB = __shfl_sync(0xffffffffu, l1, owner);
        ch_idx[r] = idx;
        ch_l[r]   = (idx < 32) ? rawA : rawB;
        if (lane == owner) { if (idx < 32) s0 = -INFINITY; else s1 = -INFINITY; }
    }
    if (lane == 0) {
        float m = ch_l[0];
#pragma unroll
        for (int r = 1; r < TOPK; r++) m = fmaxf(m, ch_l[r]);
        float w[TOPK], sum = 0.f;
#pragma unroll
        for (int r = 0; r < TOPK; r++) { w[r] = expf(ch_l[r] - m); sum += w[r]; }
        float inv = 1.f / sum;
#pragma unroll
        for (int r = 0; r < TOPK; r++) {
            int e = ch_idx[r];
            int slot = atomicAdd(&g_counts[e], 1);
            if (slot < CAP) {
                g_tok_table[e * CAP + slot] = n;
                g_w_slot[e * CAP + slot]    = w[r] * inv;
            }
        }
    }
}

// ===========================================================================
// Consumer compute cores (64M tiles; 4 consumer warps)
// ===========================================================================
// GU: warp tile 32Mx32N over 64Mx64N
__device__ __forceinline__ void gu_cons(uint32_t ub,
    uint32_t offA0, uint32_t offA1, uint32_t offB,
    float ag[2][4][4], float au[2][4][4])
{
    const uint32_t uA = ub, uBg = ub + GA, uBu = ub + GA + GB;
#pragma unroll
    for (int ks = 0; ks < 4; ks++) {
        uint32_t kb = ks * 32;
        uint32_t ah[2][4], bg[8], bu[8];
        ldsm4(ah[0], uA + offA0 + kb); ldsm4(ah[1], uA + offA1 + kb);
        ldsm4(bg,     uBg + offB + kb); ldsm4(bg + 4, uBg + offB + 16 * SST_B + kb);
        ldsm4(bu,     uBu + offB + kb); ldsm4(bu + 4, uBu + offB + 16 * SST_B + kb);
#pragma unroll
        for (int mf = 0; mf < 2; mf++)
#pragma unroll
            for (int nf = 0; nf < 4; nf++) {
                mma_f16(ag[mf][nf], ah[mf], &bg[nf * 2]);
                mma_f16(au[mf][nf], ah[mf], &bu[nf * 2]);
            }
    }
}

// DN: warp tile 32Mx64N over 64Mx128N
__device__ __forceinline__ void dn_cons(uint32_t ub,
    uint32_t offA0, uint32_t offA1, uint32_t offB,
    float ac[2][8][4])
{
    const uint32_t uA = ub, uB = ub + GA;
#pragma unroll
    for (int ks = 0; ks < 4; ks++) {
        uint32_t kb = ks * 32;
        uint32_t ah[2][4], bh[16];
        ldsm4(ah[0], uA + offA0 + kb); ldsm4(ah[1], uA + offA1 + kb);
#pragma unroll
        for (int q = 0; q < 4; q++)
            ldsm4(bh + 4 * q, uB + offB + q * 16 * SST_B + kb);
#pragma unroll
        for (int mf = 0; mf < 2; mf++)
#pragma unroll
            for (int nf = 0; nf < 8; nf++)
                mma_f16(ac[mf][nf], ah[mf], &bh[nf * 2]);
    }
}

// ===========================================================================
// GU kernel: 256 threads, 64Mx64N, K-tile 128 (2 subtiles), 2-stage ring.
// grid [0, 4096):
//   idx < 2048 : expert  e=idx>>5, t0=((idx>>3)&3)*64, f0=(idx&7)*64
//   idx >= 2048: shared  j=idx-2048: t0=(j&31)*64, f0=((j>>5)&31)*64, s=j>>10
// ===========================================================================
__global__ __launch_bounds__(256, 2)
void k_gu(const float* __restrict__ gw,  const float* __restrict__ uw,
          const float* __restrict__ sgw, const float* __restrict__ suw)
{
    extern __shared__ char sm[];
    __shared__ int toks[64];
    const int tid = threadIdx.x, wid = tid >> 5, lane = tid & 31;
    uint32_t smb = smem_u32(sm);
    const int NIT = DM / 128;     // 16
    const int idx = blockIdx.x;

    const bool is_ex = (idx < 2048);
    int e = 0, t0, f0, s = 0;
    const float *Gw, *Uw;
    if (is_ex) {
        e  = idx >> 5;
        t0 = ((idx >> 3) & 3) * 64;
        f0 = (idx & 7) * 64;
        if (t0 >= g_counts[e]) return;
        Gw = gw + ((size_t)e * FF + f0) * DM;
        Uw = uw + ((size_t)e * FF + f0) * DM;
        if (tid < 64) toks[tid] = g_tok_table[e * CAP + t0 + tid];
        __syncthreads();
    } else {
        int j = idx - 2048;
        t0 = (j & 31) * 64;
        f0 = ((j >> 5) & 31) * 64;
        s  = j >> 10;
        Gw = sgw + ((size_t)s * SFF + f0) * DM;
        Uw = suw + ((size_t)s * SFF + f0) * DM;
    }

    if (wid < 4) {
        const int wm = (wid >> 1) * 32, wn = (wid & 1) * 32;
        const uint32_t offA0 = (uint32_t)(wm + (lane & 15)) * SST_B + (lane >> 4) * 16;
        const uint32_t offA1 = offA0 + 16 * SST_B;
        const uint32_t offB  = (uint32_t)(wn + ((lane >> 4) << 3) + (lane & 7)) * SST_B
                             + ((lane >> 3) & 1) * 16;
        float ag[2][4][4] = {}, au[2][4][4] = {};
        for (int it = 0; it < NIT; it++) {
            int st = it & 1;
            BAR_SYNC(1 + st);
            uint32_t base = smb + st * GU_STG;
            gu_cons(base,          offA0, offA1, offB, ag, au);
            gu_cons(base + GU_SUB, offA0, offA1, offB, ag, au);
            BAR_ARRIVE(3 + st);
        }
        const int rl = lane >> 2, cp2 = (lane & 3) * 2;
#pragma unroll
        for (int mf = 0; mf < 2; mf++)
#pragma unroll
            for (int nf = 0; nf < 4; nf++) {
                int row = t0 + wm + mf * 16 + rl;
                int col = f0 + wn + nf * 8 + cp2;
                __half2 v0 = __floats2half2_rn(silu_f(ag[mf][nf][0]) * au[mf][nf][0],
                                               silu_f(ag[mf][nf][1]) * au[mf][nf][1]);
                __half2 v1 = __floats2half2_rn(silu_f(ag[mf][nf][2]) * au[mf][nf][2],
                                               silu_f(ag[mf][nf][3]) * au[mf][nf][3]);
                if (is_ex) {
                    __half* b0 = g_h + ((size_t)e * CAP + row) * FF + col;
                    *(__half2*)b0 = v0;
                    *(__half2*)(b0 + (size_t)8 * FF) = v1;
                } else {
                    __half* b0 = g_hs + ((size_t)s * NT + row) * SFF + col;
                    *(__half2*)b0 = v0;
                    *(__half2*)(b0 + (size_t)8 * SFF) = v1;
                }
            }
    } else {
        const int ptid = tid - 128;   // 0..127
        const __half* Axb = is_ex ? (const __half*)nullptr : g_xh + (size_t)t0 * DM;
        const __half* agp[4]; int ac8[4]; uint32_t asmo[4];
#pragma unroll
        for (int j = 0; j < 4; j++) {
            int ia = ptid + j * 128;              // [0,512) : 64 rows x 8 uint4
            int arow = ia >> 3; ac8[j] = (ia & 7) << 3;
            asmo[j] = (uint32_t)(arow * SST_B + ac8[j] * 2);
            agp[j] = is_ex ? g_xh + (size_t)toks[arow] * DM
                           : Axb + (size_t)arow * DM;
        }
        uint4 va[4]; float4 vg[8], vu[8];
        // prefetch sub0 of iter 0 (kt = 0)
#pragma unroll
        for (int j = 0; j < 4; j++)
            va[j] = *(const uint4*)(agp[j] + ac8[j]);
#pragma unroll
        for (int j = 0; j < 8; j++) {
            int ib = ptid + j * 128;              // [0,1024) : 64 rows x 16 float4
            vg[j] = *(const float4*)(Gw + (size_t)(ib >> 4) * DM + ((ib & 15) << 2));
            vu[j] = *(const float4*)(Uw + (size_t)(ib >> 4) * DM + ((ib & 15) << 2));
        }
        for (int it = 0; it < NIT; it++) {
            int st = it & 1;
            if (it >= S_STAGES) BAR_SYNC(3 + st);
            char* base = sm + st * GU_STG;
            // store sub0 from prefetch
            {
                char* A = base; char* Bg = base + GA; char* Bu = base + GA + GB;
#pragma unroll
                for (int j = 0; j < 4; j++)
                    *(uint4*)(A + asmo[j]) = va[j];
#pragma unroll
                for (int j = 0; j < 8; j++) {
                    int ib = ptid + j * 128;
                    cvt_storeBh(vg[j], Bg, ib >> 4, (ib & 15) << 2);
                    cvt_storeBh(vu[j], Bu, ib >> 4, (ib & 15) << 2);
                }
            }
            // load + store sub1 (kt = it*128 + 64)
            {
                int kt = it * 128 + 64;
#pragma unroll
                for (int j = 0; j < 4; j++)
                    va[j] = *(const uint4*)(agp[j] + kt + ac8[j]);
#pragma unroll
                for (int j = 0; j < 8; j++) {
                    int ib = ptid + j * 128;
                    vg[j] = *(const float4*)(Gw + (size_t)(ib >> 4) * DM + kt + ((ib & 15) << 2));
                    vu[j] = *(const float4*)(Uw + (size_t)(ib >> 4) * DM + kt + ((ib & 15) << 2));
                }
                char* A = base + GU_SUB; char* Bg = A + GA; char* Bu = A + GA + GB;
#pragma unroll
                for (int j = 0; j < 4; j++)
                    *(uint4*)(A + asmo[j]) = va[j];
#pragma unroll
                for (int j = 0; j < 8; j++) {
                    int ib = ptid + j * 128;
                    cvt_storeBh(vg[j], Bg, ib >> 4, (ib & 15) << 2);
                    cvt_storeBh(vu[j], Bu, ib >> 4, (ib & 15) << 2);
                }
            }
            BAR_ARRIVE(1 + st);
            // prefetch sub0 of next iter
            if (it + 1 < NIT) {
                int kt = (it + 1) * 128;
#pragma unroll
                for (int j = 0; j < 4; j++)
                    va[j] = *(const uint4*)(agp[j] + kt + ac8[j]);
#pragma unroll
                for (int j = 0; j < 8; j++) {
                    int ib = ptid + j * 128;
                    vg[j] = *(const float4*)(Gw + (size_t)(ib >> 4) * DM + kt + ((ib & 15) << 2));
                    vu[j] = *(const float4*)(Uw + (size_t)(ib >> 4) * DM + kt + ((ib & 15) << 2));
                }
            }
        }
    }
}

// ===========================================================================
// DN kernel: 256 threads, 64Mx128N, K-tile 128, 2-stage. out pre-zeroed; atomicAdd.
// grid [0, 4608):
//   idx < 512 : shared  t0=(idx&31)*64, d0=(idx>>5)*128, NIT=32 (s=it>>4)
//   idx >= 512: expert  j=idx-512: e=j>>6, t0=((j>>4)&3)*64, d0=(j&15)*128, NIT=4
// ===========================================================================
__global__ __launch_bounds__(256, 2)
void k_dn(const float* __restrict__ sdw, const float* __restrict__ dw,
          float* __restrict__ out)
{
    extern __shared__ char sm[];
    const int tid = threadIdx.x, wid = tid >> 5, lane = tid & 31;
    uint32_t smb = smem_u32(sm);
    const int idx = blockIdx.x;

    const bool is_sh = (idx < 512);
    int e = 0, t0, d0, NIT;
    if (is_sh) {
        t0 = (idx & 31) * 64; d0 = (idx >> 5) * 128; NIT = 32;
    } else {
        int j = idx - 512;
        e = j >> 6; t0 = ((j >> 4) & 3) * 64; d0 = (j & 15) * 128; NIT = FF / 128;
        if (t0 >= g_counts[e]) return;
    }

    if (wid < 4) {
        const int wm = (wid >> 1) * 32, wn = (wid & 1) * 64;
        const uint32_t offA0 = (uint32_t)(wm + (lane & 15)) * SST_B + (lane >> 4) * 16;
        const uint32_t offA1 = offA0 + 16 * SST_B;
        const uint32_t offB  = (uint32_t)(wn + ((lane >> 4) << 3) + (lane & 7)) * SST_B
                             + ((lane >> 3) & 1) * 16;
        float ac[2][8][4] = {};
        for (int it = 0; it < NIT; it++) {
            int st = it & 1;
            BAR_SYNC(1 + st);
            uint32_t base = smb + st * DN_STG;
            dn_cons(base,          offA0, offA1, offB, ac);
            dn_cons(base + DN_SUB, offA0, offA1, offB, ac);
            BAR_ARRIVE(3 + st);
        }
        const int rl = lane >> 2, cp2 = (lane & 3) * 2;
        if (is_sh) {
#pragma unroll
            for (int mf = 0; mf < 2; mf++)
#pragma unroll
                for (int nf = 0; nf < 8; nf++) {
                    int row = t0 + wm + mf * 16 + rl;
                    int col = d0 + wn + nf * 8 + cp2;
                    float* b0 = out + (size_t)row * DM + col;
                    atomicAdd(b0,     ac[mf][nf][0]);
                    atomicAdd(b0 + 1, ac[mf][nf][1]);
                    atomicAdd(b0 + (size_t)8 * DM,     ac[mf][nf][2]);
                    atomicAdd(b0 + (size_t)8 * DM + 1, ac[mf][nf][3]);
                }
        } else {
#pragma unroll
            for (int mf = 0; mf < 2; mf++) {
                int s0i = t0 + wm + mf * 16 + rl;
                int s1i = s0i + 8;
                float w0 = g_w_slot[e * CAP + s0i];
                float w1 = g_w_slot[e * CAP + s1i];
                int   k0 = g_tok_table[e * CAP + s0i];
                int   k1 = g_tok_table[e * CAP + s1i];
#pragma unroll
                for (int nf = 0; nf < 8; nf++) {
                    int col = d0 + wn + nf * 8 + cp2;
                    if (w0 != 0.f) {
                        float* p = out + (size_t)k0 * DM + col;
                        atomicAdd(p,     w0 * ac[mf][nf][0]);
                        atomicAdd(p + 1, w0 * ac[mf][nf][1]);
                    }
                    if (w1 != 0.f) {
                        float* p = out + (size_t)k1 * DM + col;
                        atomicAdd(p,     w1 * ac[mf][nf][2]);
                        atomicAdd(p + 1, w1 * ac[mf][nf][3]);
                    }
                }
            }
        }
    } else {
        const int ptid = tid - 128;   // 0..127
        int arow[4], ac8[4]; uint32_t asmo[4];
#pragma unroll
        for (int j = 0; j < 4; j++) {
            int ia = ptid + j * 128;              // 64 rows x 8 uint4
            arow[j] = ia >> 3; ac8[j] = (ia & 7) << 3;
            asmo[j] = (uint32_t)(arow[j] * SST_B + ac8[j] * 2);
        }
        const __half* Aex = g_h + ((size_t)e * CAP + t0) * FF;
        const float*  Bex = dw  + ((size_t)e * DM + d0) * FF;
        uint4 va[4]; float4 vb[16];
        // prefetch sub0 of iter 0
        if (is_sh) {
#pragma unroll
            for (int j = 0; j < 4; j++)
                va[j] = *(const uint4*)(g_hs + ((size_t)t0 + arow[j]) * SFF + ac8[j]);
#pragma unroll
            for (int j = 0; j < 16; j++) {
                int ib = ptid + j * 128;          // 128 rows x 16 float4
                vb[j] = *(const float4*)(sdw + ((size_t)d0 + (ib >> 4)) * SFF + ((ib & 15) << 2));
            }
        } else {
#pragma unroll
            for (int j = 0; j < 4; j++)
                va[j] = *(const uint4*)(Aex + (size_t)arow[j] * FF + ac8[j]);
#pragma unroll
            for (int j = 0; j < 16; j++) {
                int ib = ptid + j * 128;
                vb[j] = *(const float4*)(Bex + (size_t)(ib >> 4) * FF + ((ib & 15) << 2));
            }
        }
        for (int it = 0; it < NIT; it++) {
            int st = it & 1;
            if (it >= S_STAGES) BAR_SYNC(3 + st);
            char* base = sm + st * DN_STG;
            // store sub0 from prefetch
            {
                char* A = base; char* B = base + GA;
#pragma unroll
                for (int j = 0; j < 4; j++)
                    *(uint4*)(A + asmo[j]) = va[j];
#pragma unroll
                for (int j = 0; j < 16; j++) {
                    int ib = ptid + j * 128;
                    cvt_storeBh(vb[j], B, ib >> 4, (ib & 15) << 2);
                }
            }
            // load + store sub1
            {
                if (is_sh) {
                    int s2 = it >> 4, kt = (it & 15) * 128 + 64;
#pragma unroll
                    for (int j = 0; j < 4; j++)
                        va[j] = *(const uint4*)(g_hs + ((size_t)s2 * NT + t0 + arow[j]) * SFF + kt + ac8[j]);
#pragma unroll
                    for (int j = 0; j < 16; j++) {
                        int ib = ptid + j * 128;
                        vb[j] = *(const float4*)(sdw + ((size_t)s2 * DM + d0 + (ib >> 4)) * SFF + kt + ((ib & 15) << 2));
                    }
                } else {
                    int kt = it * 128 + 64;
#pragma unroll
                    for (int j = 0; j < 4; j++)
                        va[j] = *(const uint4*)(Aex + (size_t)arow[j] * FF + kt + ac8[j]);
#pragma unroll
                    for (int j = 0; j < 16; j++) {
                        int ib = ptid + j * 128;
                        vb[j] = *(const float4*)(Bex + (size_t)(ib >> 4) * FF + kt + ((ib & 15) << 2));
                    }
                }
                char* A = base + DN_SUB; char* B = A + GA;
#pragma unroll
                for (int j = 0; j < 4; j++)
                    *(uint4*)(A + asmo[j]) = va[j];
#pragma unroll
                for (int j = 0; j < 16; j++) {
                    int ib = ptid + j * 128;
                    cvt_storeBh(vb[j], B, ib >> 4, (ib & 15) << 2);
                }
            }
            BAR_ARRIVE(1 + st);
            // prefetch sub0 of next iter
            if (it + 1 < NIT) {
                if (is_sh) {
                    int s2 = (it + 1) >> 4, kt = ((it + 1) & 15) * 128;
#pragma unroll
                    for (int j = 0; j < 4; j++)
                        va[j] = *(const uint4*)(g_hs + ((size_t)s2 * NT + t0 + arow[j]) * SFF + kt + ac8[j]);
#pragma unroll
                    for (int j = 0; j < 16; j++) {
                        int ib = ptid + j * 128;
                        vb[j] = *(const float4*)(sdw + ((size_t)s2 * DM + d0 + (ib >> 4)) * SFF + kt + ((ib & 15) << 2));
                    }
                } else {
                    int kt = (it + 1) * 128;
#pragma unroll
                    for (int j = 0; j < 4; j++)
                        va[j] = *(const uint4*)(Aex + (size_t)arow[j] * FF + kt + ac8[j]);
#pragma unroll
                    for (int j = 0; j < 16; j++) {
                        int ib = ptid + j * 128;
                        vb[j] = *(const float4*)(Bex + (size_t)(ib >> 4) * FF + kt + ((ib & 15) << 2));
                    }
                }
            }
        }
    }
}

// ===========================================================================
// Launch
// ===========================================================================
extern "C" void kernel_launch(void* const* d_in, const int* in_sizes, int n_in,
                              void* d_out, int out_size)
{
    const float* x      = (const float*)d_in[0];
    const float* rw     = (const float*)d_in[1];
    const float* rbias  = (const float*)d_in[2];
    const float* gate_w = (const float*)d_in[3];
    const float* up_w   = (const float*)d_in[4];
    const float* down_w = (const float*)d_in[5];
    const float* sg_w   = (const float*)d_in[6];
    const float* su_w   = (const float*)d_in[7];
    const float* sd_w   = (const float*)d_in[8];
    float* out = (float*)d_out;

    cudaFuncSetAttribute(k_gu, cudaFuncAttributeMaxDynamicSharedMemorySize, GU_SMEM);
    cudaFuncSetAttribute(k_dn, cudaFuncAttributeMaxDynamicSharedMemorySize, DN_SMEM);

    k_cvt_x<<<NT * DM / 1024, 256>>>(x, out);
    k_router_logits<<<NT / RBM, 256>>>(x, rw);
    k_topk_dispatch<<<NT, 32>>>(rbias);

    k_gu<<<4096, 256, GU_SMEM>>>(gate_w, up_w, sg_w, su_w);
    k_dn<<<4608, 256, DN_SMEM>>>(sd_w, down_w, out);
}

// round 16
// speedup vs baseline: 1.3667x; 1.3667x over previous
#include <cuda_runtime.h>
#include <cuda_fp16.h>
#include <math.h>
#include <stdint.h>

// ---------------------------------------------------------------------------
// Problem constants
// ---------------------------------------------------------------------------
#define NT   2048
#define DM   2048
#define NE   64
#define TOPK 4
#define FF   512
#define NS   2
#define SFF  2048
#define CAP  256
#define NP   (NT * TOPK)

// ---------------------------------------------------------------------------
// Device scratch
// ---------------------------------------------------------------------------
__device__ float  g_logits[NT * NE];
__device__ int    g_tok_table[NE * CAP];
__device__ float  g_w_slot[NE * CAP];
__device__ int    g_counts[NE];
__device__ __half g_xh[NT * DM];
__device__ __half g_h [NE * CAP * FF];
__device__ __half g_hs[NS * NT * SFF];

// ---------------------------------------------------------------------------
// Helpers
// ---------------------------------------------------------------------------
__device__ __forceinline__ uint32_t smem_u32(const void* p) {
    uint32_t a;
    asm("{ .reg .u64 t; cvta.to.shared.u64 t, %1; cvt.u32.u64 %0, t; }" : "=r"(a) : "l"(p));
    return a;
}
__device__ __forceinline__ void ldsm4(uint32_t r[4], uint32_t a) {
    asm volatile("ldmatrix.sync.aligned.m8n8.x4.shared.b16 {%0,%1,%2,%3}, [%4];"
        : "=r"(r[0]), "=r"(r[1]), "=r"(r[2]), "=r"(r[3]) : "r"(a));
}
__device__ __forceinline__ void mma_f16(float c[4], const uint32_t a[4], const uint32_t b[2]) {
    asm volatile("mma.sync.aligned.m16n8k16.row.col.f32.f16.f16.f32 "
        "{%0,%1,%2,%3}, {%4,%5,%6,%7}, {%8,%9}, {%0,%1,%2,%3};"
        : "+f"(c[0]), "+f"(c[1]), "+f"(c[2]), "+f"(c[3])
        : "r"(a[0]), "r"(a[1]), "r"(a[2]), "r"(a[3]), "r"(b[0]), "r"(b[1]));
}
__device__ __forceinline__ uint32_t h2u(__half2 h) { return *(uint32_t*)&h; }

#define SST_B 144

__device__ __forceinline__ void cvt_storeBh(float4 v, char* hi, int r, int c4) {
    __half2 h0 = __floats2half2_rn(v.x, v.y);
    __half2 h1 = __floats2half2_rn(v.z, v.w);
    *(uint2*)(hi + (uint32_t)(r * SST_B + c4 * 2)) = make_uint2(h2u(h0), h2u(h1));
}
__device__ __forceinline__ float silu_f(float g) { return g / (1.f + expf(-g)); }

// Stage layouts: 128M tiles; each stage = TWO 64-K subtiles; 2-stage ring.
#define ABYTES 18432                       // A: 128 rows * 144B
#define BBYTES  9216                       // B: 64 rows * 144B
#define GU_SUB (ABYTES + 2 * BBYTES)       // 36864 : A | Bg | Bu
#define DN_SUB (2 * ABYTES)                // 36864 : A | B(128 rows)
#define GU_STG (2 * GU_SUB)                // 73728
#define DN_STG (2 * DN_SUB)                // 73728
#define S_STAGES 2
#define GU_SMEM (S_STAGES * GU_STG)        // 147456
#define DN_SMEM (S_STAGES * DN_STG)        // 147456

// Named barriers: FULL(s)=1+s (1..2), EMPTY(s)=3+s (3..4)
#define BAR_SYNC(id)   asm volatile("bar.sync %0, 512;"   :: "r"(id) : "memory")
#define BAR_ARRIVE(id) asm volatile("bar.arrive %0, 512;" :: "r"(id) : "memory")

// ===========================================================================
// 0) x -> fp16, zero counts/tables/out
// ===========================================================================
__global__ __launch_bounds__(256)
void k_cvt_x(const float* __restrict__ x, float* __restrict__ out)
{
    int gtid = blockIdx.x * 256 + threadIdx.x;
    if (blockIdx.x == 0 && threadIdx.x < NE) g_counts[threadIdx.x] = 0;
    if (gtid < NE * CAP) {
        g_tok_table[gtid] = 0;
        g_w_slot[gtid]    = 0.f;
    }
    int i = gtid * 4;
    float4 v = *(const float4*)(x + i);
    __half2 h0 = __floats2half2_rn(v.x, v.y);
    __half2 h1 = __floats2half2_rn(v.z, v.w);
    *(uint2*)(g_xh + i) = make_uint2(h2u(h0), h2u(h1));
    *(float4*)(out + i) = make_float4(0.f, 0.f, 0.f, 0.f);
}

// ===========================================================================
// 1) Router logits (SIMT fp32)
// ===========================================================================
#define RBM 64
#define RBK 16
__global__ __launch_bounds__(256)
void k_router_logits(const float* __restrict__ x, const float* __restrict__ rw)
{
    __shared__ __align__(16) float As[RBK][RBM];
    __shared__ __align__(16) float Bs[RBK][RBM];
    const int tid = threadIdx.x;
    const int t0  = blockIdx.x * RBM;
    const int lr  = tid >> 2, lk = (tid & 3) * 4;
    const int ty4 = (tid >> 4) * 4, tx4 = (tid & 15) * 4;
    float acc[4][4];
#pragma unroll
    for (int i = 0; i < 4; i++)
#pragma unroll
        for (int j = 0; j < 4; j++) acc[i][j] = 0.f;
    for (int kt = 0; kt < DM; kt += RBK) {
        float4 a = *(const float4*)(x + (size_t)(t0 + lr) * DM + kt + lk);
        As[lk+0][lr] = a.x; As[lk+1][lr] = a.y; As[lk+2][lr] = a.z; As[lk+3][lr] = a.w;
        float4 b = *(const float4*)(rw + (size_t)lr * DM + kt + lk);
        Bs[lk+0][lr] = b.x; Bs[lk+1][lr] = b.y; Bs[lk+2][lr] = b.z; Bs[lk+3][lr] = b.w;
        __syncthreads();
#pragma unroll
        for (int k = 0; k < RBK; k++) {
            float4 av = *(const float4*)&As[k][ty4];
            float4 bv = *(const float4*)&Bs[k][tx4];
            float a4[4] = {av.x, av.y, av.z, av.w};
            float b4[4] = {bv.x, bv.y, bv.z, bv.w};
#pragma unroll
            for (int i = 0; i < 4; i++)
#pragma unroll
                for (int j = 0; j < 4; j++) acc[i][j] += a4[i] * b4[j];
        }
        __syncthreads();
    }
#pragma unroll
    for (int i = 0; i < 4; i++)
#pragma unroll
        for (int j = 0; j < 4; j++)
            g_logits[(size_t)(t0 + ty4 + i) * NE + tx4 + j] = acc[i][j];
}

// ===========================================================================
// 2) Top-k + dispatch fused (1 warp / token)
// ===========================================================================
__global__ void k_topk_dispatch(const float* __restrict__ bias)
{
    const int n = blockIdx.x, lane = threadIdx.x;
    float l0 = g_logits[n * NE + lane];
    float l1 = g_logits[n * NE + 32 + lane];
    float s0 = l0 + bias[lane];
    float s1 = l1 + bias[32 + lane];
    int ch_idx[TOPK]; float ch_l[TOPK];
#pragma unroll
    for (int r = 0; r < TOPK; r++) {
        float v = s0; int idx = lane;
        if (s1 > v) { v = s1; idx = lane + 32; }
#pragma unroll
        for (int off = 16; off > 0; off >>= 1) {
            float ov = __shfl_xor_sync(0xffffffffu, v, off);
            int   oi = __shfl_xor_sync(0xffffffffu, idx, off);
            if (ov > v || (ov == v && oi < idx)) { v = ov; idx = oi; }
        }
        int owner = (idx < 32) ? idx : (idx - 32);
        float rawA = __shfl_sync(0xffffffffu, l0, owner);
        float rawB = __shfl_sync(0xffffffffu, l1, owner);
        ch_idx[r] = idx;
        ch_l[r]   = (idx < 32) ? rawA : rawB;
        if (lane == owner) { if (idx < 32) s0 = -INFINITY; else s1 = -INFINITY; }
    }
    if (lane == 0) {
        float m = ch_l[0];
#pragma unroll
        for (int r = 1; r < TOPK; r++) m = fmaxf(m, ch_l[r]);
        float w[TOPK], sum = 0.f;
#pragma unroll
        for (int r = 0; r < TOPK; r++) { w[r] = expf(ch_l[r] - m); sum += w[r]; }
        float inv = 1.f / sum;
#pragma unroll
        for (int r = 0; r < TOPK; r++) {
            int e = ch_idx[r];
            int slot = atomicAdd(&g_counts[e], 1);
            if (slot < CAP) {
                g_tok_table[e * CAP + slot] = n;
                g_w_slot[e * CAP + slot]    = w[r] * inv;
            }
        }
    }
}

// ===========================================================================
// Consumer compute cores (identical to R13 — bitwise-stable)
// ===========================================================================
__device__ __forceinline__ void gu_cons(uint32_t ub,
    uint32_t offA0, uint32_t offA1, uint32_t offB,
    float ag[2][4][4], float au[2][4][4])
{
    const uint32_t uA = ub, uBg = ub + ABYTES, uBu = uBg + BBYTES;
#pragma unroll
    for (int ks = 0; ks < 4; ks++) {
        uint32_t kb = ks * 32;
        uint32_t ah[2][4], bg[8], bu[8];
        ldsm4(ah[0], uA + offA0 + kb); ldsm4(ah[1], uA + offA1 + kb);
        ldsm4(bg,     uBg + offB + kb); ldsm4(bg + 4, uBg + offB + 16 * SST_B + kb);
        ldsm4(bu,     uBu + offB + kb); ldsm4(bu + 4, uBu + offB + 16 * SST_B + kb);
#pragma unroll
        for (int mf = 0; mf < 2; mf++)
#pragma unroll
            for (int nf = 0; nf < 4; nf++) {
                mma_f16(ag[mf][nf], ah[mf], &bg[nf * 2]);
                mma_f16(au[mf][nf], ah[mf], &bu[nf * 2]);
            }
    }
}

__device__ __forceinline__ void dn_cons(uint32_t ub,
    uint32_t offA0, uint32_t offA1, uint32_t offB,
    float ac[2][8][4])
{
    const uint32_t uA = ub, uB = ub + ABYTES;
#pragma unroll
    for (int ks = 0; ks < 4; ks++) {
        uint32_t kb = ks * 32;
        uint32_t ah[2][4], bh[16];
        ldsm4(ah[0], uA + offA0 + kb); ldsm4(ah[1], uA + offA1 + kb);
#pragma unroll
        for (int q = 0; q < 4; q++)
            ldsm4(bh + 4 * q, uB + offB + q * 16 * SST_B + kb);
#pragma unroll
        for (int mf = 0; mf < 2; mf++)
#pragma unroll
            for (int nf = 0; nf < 8; nf++)
                mma_f16(ac[mf][nf], ah[mf], &bh[nf * 2]);
    }
}

// ===========================================================================
// Merged GU kernel: linear grid [0, 2048). K-tile = 128 (two 64-K subtiles).
// ===========================================================================
__global__ __launch_bounds__(512)
void k_gu(const float* __restrict__ gw,  const float* __restrict__ uw,
          const float* __restrict__ sgw, const float* __restrict__ suw)
{
    extern __shared__ char sm[];
    __shared__ int toks[128];
    const int tid = threadIdx.x, wid = tid >> 5, lane = tid & 31;
    uint32_t smb = smem_u32(sm);
    const int NIT = DM / 128;     // 16
    const int idx = blockIdx.x;

    const bool is_ex = (idx < 1024);
    int e = 0, t0, f0, s = 0;
    const float *Gw, *Uw;
    if (is_ex) {
        e  = idx >> 4;
        t0 = ((idx >> 3) & 1) * 128;
        f0 = (idx & 7) * 64;
        if (t0 >= g_counts[e]) return;
        Gw = gw + ((size_t)e * FF + f0) * DM;
        Uw = uw + ((size_t)e * FF + f0) * DM;
        if (tid < 128) toks[tid] = g_tok_table[e * CAP + t0 + tid];
        __syncthreads();
    } else {
        int j = idx - 1024;
        t0 = (j & 15) * 128;
        f0 = ((j >> 4) & 31) * 64;
        s  = j >> 9;
        Gw = sgw + ((size_t)s * SFF + f0) * DM;
        Uw = suw + ((size_t)s * SFF + f0) * DM;
    }

    if (wid < 8) {
        const int wm = (wid >> 1) * 32, wn = (wid & 1) * 32;
        const uint32_t offA0 = (uint32_t)(wm + (lane & 15)) * SST_B + (lane >> 4) * 16;
        const uint32_t offA1 = offA0 + 16 * SST_B;
        const uint32_t offB  = (uint32_t)(wn + ((lane >> 4) << 3) + (lane & 7)) * SST_B
                             + ((lane >> 3) & 1) * 16;
        float ag[2][4][4] = {}, au[2][4][4] = {};
        for (int it = 0; it < NIT; it++) {
            int st = it & 1;
            BAR_SYNC(1 + st);
            uint32_t base = smb + st * GU_STG;
            gu_cons(base,          offA0, offA1, offB, ag, au);
            gu_cons(base + GU_SUB, offA0, offA1, offB, ag, au);
            BAR_ARRIVE(3 + st);
        }
        const int rl = lane >> 2, cp2 = (lane & 3) * 2;
#pragma unroll
        for (int mf = 0; mf < 2; mf++)
#pragma unroll
            for (int nf = 0; nf < 4; nf++) {
                int row = t0 + wm + mf * 16 + rl;
                int col = f0 + wn + nf * 8 + cp2;
                __half2 v0 = __floats2half2_rn(silu_f(ag[mf][nf][0]) * au[mf][nf][0],
                                               silu_f(ag[mf][nf][1]) * au[mf][nf][1]);
                __half2 v1 = __floats2half2_rn(silu_f(ag[mf][nf][2]) * au[mf][nf][2],
                                               silu_f(ag[mf][nf][3]) * au[mf][nf][3]);
                if (is_ex) {
                    __half* b0 = g_h + ((size_t)e * CAP + row) * FF + col;
                    *(__half2*)b0 = v0;
                    *(__half2*)(b0 + (size_t)8 * FF) = v1;
                } else {
                    __half* b0 = g_hs + ((size_t)s * NT + row) * SFF + col;
                    *(__half2*)b0 = v0;
                    *(__half2*)(b0 + (size_t)8 * SFF) = v1;
                }
            }
    } else {
        const int ptid = tid - 256;
        const __half* Axb = is_ex ? (const __half*)nullptr : g_xh + (size_t)t0 * DM;
        const __half* agp[4]; int ac8[4]; uint32_t asmo[4];
#pragma unroll
        for (int j = 0; j < 4; j++) {
            int ia = ptid + j * 256;
            int arow = ia >> 3; ac8[j] = (ia & 7) << 3;
            asmo[j] = (uint32_t)(arow * SST_B + ac8[j] * 2);
            agp[j] = is_ex ? g_xh + (size_t)toks[arow] * DM
                           : Axb + (size_t)arow * DM;
        }
        // full-iteration prefetch: BOTH subtiles held in registers
        uint4 va0[4], va1[4]; float4 vg0[4], vg1[4], vu0[4], vu1[4];
#pragma unroll
        for (int j = 0; j < 4; j++) {
            int ia = ptid + j * 256;
            va0[j] = *(const uint4*)(agp[j] + ac8[j]);
            vg0[j] = *(const float4*)(Gw + (size_t)(ia >> 4) * DM + ((ia & 15) << 2));
            vu0[j] = *(const float4*)(Uw + (size_t)(ia >> 4) * DM + ((ia & 15) << 2));
            va1[j] = *(const uint4*)(agp[j] + 64 + ac8[j]);
            vg1[j] = *(const float4*)(Gw + (size_t)(ia >> 4) * DM + 64 + ((ia & 15) << 2));
            vu1[j] = *(const float4*)(Uw + (size_t)(ia >> 4) * DM + 64 + ((ia & 15) << 2));
        }
        for (int it = 0; it < NIT; it++) {
            int st = it & 1;
            if (it >= S_STAGES) BAR_SYNC(3 + st);
            char* base = sm + st * GU_STG;
            {   // store sub0
                char* A = base; char* Bg = base + ABYTES; char* Bu = Bg + BBYTES;
#pragma unroll
                for (int j = 0; j < 4; j++) {
                    int ia = ptid + j * 256;
                    *(uint4*)(A + asmo[j]) = va0[j];
                    cvt_storeBh(vg0[j], Bg, ia >> 4, (ia & 15) << 2);
                    cvt_storeBh(vu0[j], Bu, ia >> 4, (ia & 15) << 2);
                }
            }
            {   // store sub1
                char* A = base + GU_SUB; char* Bg = A + ABYTES; char* Bu = Bg + BBYTES;
#pragma unroll
                for (int j = 0; j < 4; j++) {
                    int ia = ptid + j * 256;
                    *(uint4*)(A + asmo[j]) = va1[j];
                    cvt_storeBh(vg1[j], Bg, ia >> 4, (ia & 15) << 2);
                    cvt_storeBh(vu1[j], Bu, ia >> 4, (ia & 15) << 2);
                }
            }
            BAR_ARRIVE(1 + st);
            if (it + 1 < NIT) {
                int kt = (it + 1) * 128;
#pragma unroll
                for (int j = 0; j < 4; j++) {
                    int ia = ptid + j * 256;
                    va0[j] = *(const uint4*)(agp[j] + kt + ac8[j]);
                    vg0[j] = *(const float4*)(Gw + (size_t)(ia >> 4) * DM + kt + ((ia & 15) << 2));
                    vu0[j] = *(const float4*)(Uw + (size_t)(ia >> 4) * DM + kt + ((ia & 15) << 2));
                    va1[j] = *(const uint4*)(agp[j] + kt + 64 + ac8[j]);
                    vg1[j] = *(const float4*)(Gw + (size_t)(ia >> 4) * DM + kt + 64 + ((ia & 15) << 2));
                    vu1[j] = *(const float4*)(Uw + (size_t)(ia >> 4) * DM + kt + 64 + ((ia & 15) << 2));
                }
            }
        }
    }
}

// ===========================================================================
// Merged DN kernel: linear grid [0, 2304). K-tile 128. out pre-zeroed; atomicAdd.
// ===========================================================================
__global__ __launch_bounds__(512)
void k_dn(const float* __restrict__ sdw, const float* __restrict__ dw,
          float* __restrict__ out)
{
    extern __shared__ char sm[];
    const int tid = threadIdx.x, wid = tid >> 5, lane = tid & 31;
    uint32_t smb = smem_u32(sm);
    const int idx = blockIdx.x;

    const bool is_sh = (idx < 256);
    int e = 0, t0, d0, NIT;
    if (is_sh) {
        t0 = (idx & 15) * 128; d0 = (idx >> 4) * 128; NIT = 32;
    } else {
        int j = idx - 256;
        e = j >> 5; t0 = ((j >> 4) & 1) * 128; d0 = (j & 15) * 128; NIT = FF / 128;
        if (t0 >= g_counts[e]) return;
    }

    if (wid < 8) {
        const int wm = (wid >> 1) * 32, wn = (wid & 1) * 64;
        const uint32_t offA0 = (uint32_t)(wm + (lane & 15)) * SST_B + (lane >> 4) * 16;
        const uint32_t offA1 = offA0 + 16 * SST_B;
        const uint32_t offB  = (uint32_t)(wn + ((lane >> 4) << 3) + (lane & 7)) * SST_B
                             + ((lane >> 3) & 1) * 16;
        float ac[2][8][4] = {};
        for (int it = 0; it < NIT; it++) {
            int st = it & 1;
            BAR_SYNC(1 + st);
            uint32_t base = smb + st * DN_STG;
            dn_cons(base,          offA0, offA1, offB, ac);
            dn_cons(base + DN_SUB, offA0, offA1, offB, ac);
            BAR_ARRIVE(3 + st);
        }
        const int rl = lane >> 2, cp2 = (lane & 3) * 2;
        if (is_sh) {
#pragma unroll
            for (int mf = 0; mf < 2; mf++)
#pragma unroll
                for (int nf = 0; nf < 8; nf++) {
                    int row = t0 + wm + mf * 16 + rl;
                    int col = d0 + wn + nf * 8 + cp2;
                    float* b0 = out + (size_t)row * DM + col;
                    atomicAdd(b0,     ac[mf][nf][0]);
                    atomicAdd(b0 + 1, ac[mf][nf][1]);
                    atomicAdd(b0 + (size_t)8 * DM,     ac[mf][nf][2]);
                    atomicAdd(b0 + (size_t)8 * DM + 1, ac[mf][nf][3]);
                }
        } else {
#pragma unroll
            for (int mf = 0; mf < 2; mf++) {
                int s0i = t0 + wm + mf * 16 + rl;
                int s1i = s0i + 8;
                float w0 = g_w_slot[e * CAP + s0i];
                float w1 = g_w_slot[e * CAP + s1i];
                int   k0 = g_tok_table[e * CAP + s0i];
                int   k1 = g_tok_table[e * CAP + s1i];
#pragma unroll
                for (int nf = 0; nf < 8; nf++) {
                    int col = d0 + wn + nf * 8 + cp2;
                    if (w0 != 0.f) {
                        float* p = out + (size_t)k0 * DM + col;
                        atomicAdd(p,     w0 * ac[mf][nf][0]);
                        atomicAdd(p + 1, w0 * ac[mf][nf][1]);
                    }
                    if (w1 != 0.f) {
                        float* p = out + (size_t)k1 * DM + col;
                        atomicAdd(p,     w1 * ac[mf][nf][2]);
                        atomicAdd(p + 1, w1 * ac[mf][nf][3]);
                    }
                }
            }
        }
    } else {
        const int ptid = tid - 256;
        int arow[4], ac8[4]; uint32_t asmo[4];
#pragma unroll
        for (int j = 0; j < 4; j++) {
            int ia = ptid + j * 256;
            arow[j] = ia >> 3; ac8[j] = (ia & 7) << 3;
            asmo[j] = (uint32_t)(arow[j] * SST_B + ac8[j] * 2);
        }
        const __half* Aex = g_h + ((size_t)e * CAP + t0) * FF;
        const float*  Bex = dw  + ((size_t)e * DM + d0) * FF;
        uint4 va0[4], va1[4]; float4 vb0[8], vb1[8];
        // full-iteration prefetch (both subtiles)
        if (is_sh) {
#pragma unroll
            for (int j = 0; j < 4; j++) {
                va0[j] = *(const uint4*)(g_hs + ((size_t)t0 + arow[j]) * SFF + ac8[j]);
                va1[j] = *(const uint4*)(g_hs + ((size_t)t0 + arow[j]) * SFF + 64 + ac8[j]);
            }
#pragma unroll
            for (int j = 0; j < 8; j++) {
                int ib = ptid + j * 256;
                vb0[j] = *(const float4*)(sdw + ((size_t)d0 + (ib >> 4)) * SFF + ((ib & 15) << 2));
                vb1[j] = *(const float4*)(sdw + ((size_t)d0 + (ib >> 4)) * SFF + 64 + ((ib & 15) << 2));
            }
        } else {
#pragma unroll
            for (int j = 0; j < 4; j++) {
                va0[j] = *(const uint4*)(Aex + (size_t)arow[j] * FF + ac8[j]);
                va1[j] = *(const uint4*)(Aex + (size_t)arow[j] * FF + 64 + ac8[j]);
            }
#pragma unroll
            for (int j = 0; j < 8; j++) {
                int ib = ptid + j * 256;
                vb0[j] = *(const float4*)(Bex + (size_t)(ib >> 4) * FF + ((ib & 15) << 2));
                vb1[j] = *(const float4*)(Bex + (size_t)(ib >> 4) * FF + 64 + ((ib & 15) << 2));
            }
        }
        for (int it = 0; it < NIT; it++) {
            int st = it & 1;
            if (it >= S_STAGES) BAR_SYNC(3 + st);
            char* base = sm + st * DN_STG;
            {   // store sub0
                char* A = base; char* B = base + ABYTES;
#pragma unroll
                for (int j = 0; j < 4; j++)
                    *(uint4*)(A + asmo[j]) = va0[j];
#pragma unroll
                for (int j = 0; j < 8; j++) {
                    int ib = ptid + j * 256;
                    cvt_storeBh(vb0[j], B, ib >> 4, (ib & 15) << 2);
                }
            }
            {   // store sub1
                char* A = base + DN_SUB; char* B = A + ABYTES;
#pragma unroll
                for (int j = 0; j < 4; j++)
                    *(uint4*)(A + asmo[j]) = va1[j];
#pragma unroll
                for (int j = 0; j < 8; j++) {
                    int ib = ptid + j * 256;
                    cvt_storeBh(vb1[j], B, ib >> 4, (ib & 15) << 2);
                }
            }
            BAR_ARRIVE(1 + st);
            if (it + 1 < NIT) {
                if (is_sh) {
                    int s2 = (it + 1) >> 4, kt = ((it + 1) & 15) * 128;
#pragma unroll
                    for (int j = 0; j < 4; j++) {
                        va0[j] = *(const uint4*)(g_hs + ((size_t)s2 * NT + t0 + arow[j]) * SFF + kt + ac8[j]);
                        va1[j] = *(const uint4*)(g_hs + ((size_t)s2 * NT + t0 + arow[j]) * SFF + kt + 64 + ac8[j]);
                    }
#pragma unroll
                    for (int j = 0; j < 8; j++) {
                        int ib = ptid + j * 256;
                        vb0[j] = *(const float4*)(sdw + ((size_t)s2 * DM + d0 + (ib >> 4)) * SFF + kt + ((ib & 15) << 2));
                        vb1[j] = *(const float4*)(sdw + ((size_t)s2 * DM + d0 + (ib >> 4)) * SFF + kt + 64 + ((ib & 15) << 2));
                    }
                } else {
                    int kt = (it + 1) * 128;
#pragma unroll
                    for (int j = 0; j < 4; j++) {
                        va0[j] = *(const uint4*)(Aex + (size_t)arow[j] * FF + kt + ac8[j]);
                        va1[j] = *(const uint4*)(Aex + (size_t)arow[j] * FF + kt + 64 + ac8[j]);
                    }
#pragma unroll
                    for (int j = 0; j < 8; j++) {
                        int ib = ptid + j * 256;
                        vb0[j] = *(const float4*)(Bex + (size_t)(ib >> 4) * FF + kt + ((ib & 15) << 2));
                        vb1[j] = *(const float4*)(Bex + (size_t)(ib >> 4) * FF + kt + 64 + ((ib & 15) << 2));
                    }
                }
            }
        }
    }
}

// ===========================================================================
// Launch
// ===========================================================================
extern "C" void kernel_launch(void* const* d_in, const int* in_sizes, int n_in,
                              void* d_out, int out_size)
{
    const float* x      = (const float*)d_in[0];
    const float* rw     = (const float*)d_in[1];
    const float* rbias  = (const float*)d_in[2];
    const float* gate_w = (const float*)d_in[3];
    const float* up_w   = (const float*)d_in[4];
    const float* down_w = (const float*)d_in[5];
    const float* sg_w   = (const float*)d_in[6];
    const float* su_w   = (const float*)d_in[7];
    const float* sd_w   = (const float*)d_in[8];
    float* out = (float*)d_out;

    cudaFuncSetAttribute(k_gu, cudaFuncAttributeMaxDynamicSharedMemorySize, GU_SMEM);
    cudaFuncSetAttribute(k_dn, cudaFuncAttributeMaxDynamicSharedMemorySize, DN_SMEM);

    k_cvt_x<<<NT * DM / 1024, 256>>>(x, out);
    k_router_logits<<<NT / RBM, 256>>>(x, rw);
    k_topk_dispatch<<<NT, 32>>>(rbias);

    k_gu<<<2048, 512, GU_SMEM>>>(gate_w, up_w, sg_w, su_w);
    k_dn<<<2304, 512, DN_SMEM>>>(sd_w, down_w, out);
}